// round 14
// baseline (speedup 1.0000x reference)
#include <cuda_runtime.h>
#include <cuda_fp16.h>
#include <cstdint>
#include <math.h>

#define BB 4
#define NN 4096
#define KK 32
#define HH 128
#define NODES (BB*NN)

// ---------------- scratch (static, no allocation) ----------------
__device__ float g_upd[NODES * HH];          // 8 MB
__device__ float g_sbias[NODES * HH];        // 8 MB: b0 + self@W0_self per node
__device__ float g_mean[BB * HH];
__device__ float g_rstd[BB * HH];
// stats partials: 128 chunks of 32 nodes per batch
__device__ float g_ps[BB * 128 * HH];
__device__ float g_pq[BB * 128 * HH];
__device__ float g_pc[BB * 128];
// prepped fp16 weights:
//   [0, 98304)       : layers 0..2, hi-only, 32 KB each (4 quarters x 8 KB, swizzled)
//   [98304, 163840)  : W0_self hi/lo, 4 quarters x (hi 8 KB | lo 8 KB)
__device__ __align__(16) unsigned char g_Wp[163840];

// ---------------- helpers ----------------
__device__ __forceinline__ uint32_t smem_u32(const void* p) {
    uint32_t a;
    asm("{ .reg .u64 t; cvta.to.shared.u64 t, %1; cvt.u32.u64 %0, t; }"
        : "=r"(a) : "l"(p));
    return a;
}
// fast GELU: tanh form with hardware tanh.approx (sm_75+), ~6 ops.
__device__ __forceinline__ float gelu_fast(float x) {
    float x2 = x * x;
    float y  = x * fmaf(0.03567740814f, x2, 0.7978845608f);
    float t;
    asm("tanh.approx.f32 %0, %1;" : "=f"(t) : "f"(y));
    float h = 0.5f * x;
    return fmaf(h, t, h);
}
__device__ __forceinline__ uint32_t packh2(float x, float y) {
    __half2 h = __floats2half2_rn(x, y);
    return *(uint32_t*)&h;
}
__device__ __forceinline__ void ldm4(uint32_t* r, uint32_t addr) {
    asm volatile("ldmatrix.sync.aligned.m8n8.x4.shared.b16 {%0,%1,%2,%3}, [%4];"
        : "=r"(r[0]), "=r"(r[1]), "=r"(r[2]), "=r"(r[3]) : "r"(addr));
}
__device__ __forceinline__ void mma_f16(float* c, const uint32_t* a, const uint32_t* b) {
    asm volatile(
        "mma.sync.aligned.m16n8k16.row.col.f32.f16.f16.f32 "
        "{%0,%1,%2,%3}, {%4,%5,%6,%7}, {%8,%9}, {%0,%1,%2,%3};"
        : "+f"(c[0]), "+f"(c[1]), "+f"(c[2]), "+f"(c[3])
        : "r"(a[0]), "r"(a[1]), "r"(a[2]), "r"(a[3]), "r"(b[0]), "r"(b[1]));
}
#define CP_ASYNC16(dst, src) \
    asm volatile("cp.async.cg.shared.global [%0], [%1], 16;" \
        :: "r"(dst), "l"(src) : "memory")
#define CP_COMMIT() asm volatile("cp.async.commit_group;" ::: "memory")
#define CP_WAIT1()  asm volatile("cp.async.wait_group 1;" ::: "memory")
#define CP_WAIT0()  asm volatile("cp.async.wait_group 0;" ::: "memory")

// ---------------- prep: W -> fp16, swizzled, quartered ----------------
__global__ void prep_weights(const float* __restrict__ W0,
                             const float* __restrict__ W1,
                             const float* __restrict__ W2)
{
    int i = blockIdx.x * blockDim.x + threadIdx.x;
    if (i >= 4 * HH * HH) return;
    int lyr = i >> 14, r = i & 16383, n = r >> 7, k = r & 127;
    float v;
    if (lyr == 0)      v = W0[k * HH + n];            // src block rows 0..127
    else if (lyr == 1) v = W1[k * HH + n];
    else if (lyr == 2) v = W2[k * HH + n];
    else               v = W0[(HH + k) * HH + n];     // self block rows 128..255
    __half h = __float2half_rn(v);
    int q = n >> 5, nl = n & 31;
    int byte = nl * 256 + (((k >> 3) ^ (nl & 7)) << 4) + ((k & 7) << 1);
    if (lyr < 3) {
        *(__half*)(g_Wp + lyr * 32768 + q * 8192 + byte) = h;
    } else {
        __half lo = __float2half_rn(v - __half2float(h));
        unsigned char* base = g_Wp + 98304 + q * 16384;
        *(__half*)(base + byte)        = h;
        *(__half*)(base + 8192 + byte) = lo;
    }
}

// ---------------- self-bias mini-GEMM: g_sbias = b0 + self@W0_self ----------------
#define SB_SMEM 98304
__global__ __launch_bounds__(128)
void sbias_kernel(const float* __restrict__ enc, const float* __restrict__ mask,
                  const float* __restrict__ b0)
{
    extern __shared__ char smem[];
    uint32_t sb = smem_u32(smem);
    const int tid = threadIdx.x;
    const int w = tid >> 5, l = tid & 31;
    const int base_node = blockIdx.x << 7;

    // gather masked self rows into fp16 A plane
    {
        const int node = base_node + tid;
        const float mm = mask[node];
        const float4* rp = (const float4*)(enc + (size_t)node * HH);
        const int rp7 = tid & 7;
        #pragma unroll
        for (int c = 0; c < 16; c++) {
            float4 v0 = rp[2 * c], v1 = rp[2 * c + 1];
            uint32_t u0 = packh2(v0.x * mm, v0.y * mm);
            uint32_t u1 = packh2(v0.z * mm, v0.w * mm);
            uint32_t u2 = packh2(v1.x * mm, v1.y * mm);
            uint32_t u3 = packh2(v1.z * mm, v1.w * mm);
            uint32_t off = (uint32_t)tid * 256 + (uint32_t)((c ^ rp7) << 4);
            *(uint4*)(smem + off) = make_uint4(u0, u1, u2, u3);
        }
    }
    // stage full W0_self hi/lo: 64 KB at +32768
    {
        const uint4* src = (const uint4*)(g_Wp + 98304);
        uint4* dst = (uint4*)(smem + 32768);
        #pragma unroll
        for (int i = 0; i < 32; i++) dst[tid + 128 * i] = src[tid + 128 * i];
    }
    __syncthreads();

    const int rA0 = (w << 5) + (l & 15), rA1 = rA0 + 16;
    const uint32_t cselA = (uint32_t)(l >> 4);
    const uint32_t baseA0 = sb + (uint32_t)rA0 * 256;
    const uint32_t baseA1 = sb + (uint32_t)rA1 * 256;
    const uint32_t parA0 = (uint32_t)(rA0 & 7), parA1 = (uint32_t)(rA1 & 7);
    const int rB = (l & 7) + ((l >> 4) << 3);
    const uint32_t cselB = (uint32_t)((l >> 3) & 1);
    const uint32_t parB = (uint32_t)(rB & 7);
    const int c2 = (l & 3) << 1;

    float acc[2][16][4];
    #pragma unroll
    for (int nt = 0; nt < 16; nt++) {
        float bx = b0[8 * nt + c2], by = b0[8 * nt + c2 + 1];
        #pragma unroll
        for (int m = 0; m < 2; m++) {
            acc[m][nt][0] = bx; acc[m][nt][1] = by;
            acc[m][nt][2] = bx; acc[m][nt][3] = by;
        }
    }

    #pragma unroll
    for (int q = 0; q < 4; q++) {
        const uint32_t baseBq = sb + 32768 + (uint32_t)q * 16384 + (uint32_t)rB * 256;
        #pragma unroll
        for (int ks = 0; ks < 8; ks++) {
            uint32_t ah0[4], ah1[4], bh[2][4], bl[2][4];
            const uint32_t kA = (uint32_t)(2 * ks) + cselA;
            const uint32_t kB = (uint32_t)(2 * ks) + cselB;
            ldm4(ah0, baseA0 + ((kA ^ parA0) << 4));
            ldm4(ah1, baseA1 + ((kA ^ parA1) << 4));
            #pragma unroll
            for (int jj = 0; jj < 2; jj++) {
                ldm4(bh[jj], baseBq + jj * 4096 + ((kB ^ parB) << 4));
                ldm4(bl[jj], baseBq + 8192 + jj * 4096 + ((kB ^ parB) << 4));
            }
            #pragma unroll
            for (int tt = 0; tt < 4; tt++) {
                const int nt = 4 * q + tt;
                const uint32_t* bH = &bh[tt >> 1][(tt & 1) << 1];
                const uint32_t* bL = &bl[tt >> 1][(tt & 1) << 1];
                mma_f16(acc[0][nt], ah0, bH);
                mma_f16(acc[1][nt], ah1, bH);
                mma_f16(acc[0][nt], ah0, bL);
                mma_f16(acc[1][nt], ah1, bL);
            }
        }
    }

    #pragma unroll
    for (int m = 0; m < 2; m++) {
        const int row0 = base_node + (w << 5) + (m << 4) + (l >> 2);
        #pragma unroll
        for (int nt = 0; nt < 16; nt++) {
            *(float2*)&g_sbias[(size_t)row0 * HH + 8 * nt + c2] =
                make_float2(acc[m][nt][0], acc[m][nt][1]);
            *(float2*)&g_sbias[(size_t)(row0 + 8) * HH + 8 * nt + c2] =
                make_float2(acc[m][nt][2], acc[m][nt][3]);
        }
    }
}

// ---------------- main fused kernel ----------------
// 128 threads; hi-only; 16 KB half-layer double-buffered staging (6 stages);
// ks-outer within each half; smem 74,272 B -> 3 CTAs/SM (launch_bounds(128,3)).
// smem layout (bytes)
#define OFF_A     0        // 32768 : A fp16 plane, 128 rows x 256B, chunk-swizzled
#define OFF_B     32768    // 32768 : double-buffered half-layer weights (2 x 16 KB)
#define OFF_SELF  65536    // 2048
#define OFF_SBIAS 67584    // 2048
#define OFF_MSUM  69632    // 2048 : [4 warps][128]
#define OFF_W256  71680    // 512
#define OFF_BV    72192    // 1024
#define OFF_DE    73216    // 512
#define OFF_VLD   73728    // 512
#define OFF_INV   74240    // 16
#define OFF_NM    74256    // 16
#define SMEM_BYTES 74272

__global__ __launch_bounds__(128, 3)
void mpnn_tc(const float* __restrict__ enc, const float* __restrict__ mask,
             const float* __restrict__ dist, const int* __restrict__ eidx,
             const float* __restrict__ W0,
             const float* __restrict__ b1, const float* __restrict__ b2)
{
    extern __shared__ char smem[];
    uint32_t sb = smem_u32(smem);
    float* smf = (float*)smem;
    const int tid = threadIdx.x;
    const int w = tid >> 5, l = tid & 31;
    const int base_node = blockIdx.x << 2;
    const int batch = base_node >> 12;

    // prologue: prefetch weight stage 0 (16 KB) immediately
    {
        const char* src = (const char*)g_Wp + tid * 16;
        uint32_t dst = sb + OFF_B + tid * 16;
        #pragma unroll
        for (int i = 0; i < 8; i++)
            CP_ASYNC16(dst + i * 2048, src + i * 2048);
        CP_COMMIT();
    }

    // ---- per-edge metadata (thread = edge row) ----
    const int ei = eidx[base_node * KK + tid];
    const int gsrc = batch * NN + ((ei < 0) ? 0 : ei);
    const float smask = mask[gsrc];
    smf[(OFF_DE  >> 2) + tid] = dist[base_node * KK + tid];
    smf[(OFF_VLD >> 2) + tid] = (ei >= 0) ? 1.0f : 0.0f;
    unsigned cnt = __reduce_add_sync(0xffffffffu, (ei >= 0) ? 1u : 0u);
    if (l == 0) smf[(OFF_INV >> 2) + w] = 1.0f / ((cnt == 0) ? 1.0f : (float)cnt);

    #pragma unroll
    for (int g = 0; g < 4; g++) {
        float mm = mask[base_node + g];
        smf[(OFF_SELF  >> 2) + g * HH + tid] =
            enc[(size_t)(base_node + g) * HH + tid] * mm;
        smf[(OFF_SBIAS >> 2) + g * HH + tid] =
            g_sbias[(size_t)(base_node + g) * HH + tid];
    }
    if (tid < 4) smf[(OFF_NM >> 2) + tid] = mask[base_node + tid];
    smf[(OFF_W256 >> 2) + tid]      = W0[256 * HH + tid];
    smf[(OFF_BV   >> 2) + tid]      = b1[tid];
    smf[(OFF_BV   >> 2) + HH + tid] = b2[tid];

    // ---- gather neighbor features -> A plane (fp16, swizzled) ----
    {
        const float4* rp = (const float4*)(enc + (size_t)gsrc * HH);
        const int rp7 = tid & 7;
        #pragma unroll
        for (int c = 0; c < 16; c++) {
            float4 v0 = rp[2 * c], v1 = rp[2 * c + 1];
            uint32_t u0 = packh2(v0.x * smask, v0.y * smask);
            uint32_t u1 = packh2(v0.z * smask, v0.w * smask);
            uint32_t u2 = packh2(v1.x * smask, v1.y * smask);
            uint32_t u3 = packh2(v1.z * smask, v1.w * smask);
            uint32_t off = (uint32_t)tid * 256 + (uint32_t)((c ^ rp7) << 4);
            *(uint4*)(smem + OFF_A + off) = make_uint4(u0, u1, u2, u3);
        }
    }

    // ---- lane constants for ldmatrix addressing ----
    const int rA0 = (w << 5) + (l & 15), rA1 = rA0 + 16;
    const uint32_t cselA = (uint32_t)(l >> 4);
    const uint32_t baseA0 = sb + OFF_A + (uint32_t)rA0 * 256;
    const uint32_t baseA1 = sb + OFF_A + (uint32_t)rA1 * 256;
    const uint32_t parA0 = (uint32_t)(rA0 & 7), parA1 = (uint32_t)(rA1 & 7);
    const int rB = (l & 7) + ((l >> 4) << 3);
    const uint32_t cselB = (uint32_t)((l >> 3) & 1);
    const uint32_t parB = (uint32_t)(rB & 7);
    const int c2 = (l & 3) << 1;

    __syncthreads();   // A plane + small tables visible

    float acc[2][16][4];
    int s = 0;   // global weight stage 0..5 (16 KB half-layers)

    #pragma unroll 1
    for (int layer = 0; layer < 3; layer++) {
        // ---- init acc with bias ----
        if (layer == 0) {
            #pragma unroll
            for (int nt = 0; nt < 16; nt++) {
                float2 sb2 = *(float2*)&smf[(OFF_SBIAS >> 2) + w * HH + 8 * nt + c2];
                float2 w2  = *(float2*)&smf[(OFF_W256  >> 2) + 8 * nt + c2];
                #pragma unroll
                for (int m = 0; m < 2; m++) {
                    float dem = smf[(OFF_DE >> 2) + (w << 5) + (l >> 2) + 16 * m];
                    float dem8 = smf[(OFF_DE >> 2) + (w << 5) + (l >> 2) + 16 * m + 8];
                    acc[m][nt][0] = fmaf(dem,  w2.x, sb2.x);
                    acc[m][nt][1] = fmaf(dem,  w2.y, sb2.y);
                    acc[m][nt][2] = fmaf(dem8, w2.x, sb2.x);
                    acc[m][nt][3] = fmaf(dem8, w2.y, sb2.y);
                }
            }
        } else {
            const float* bv = &smf[(OFF_BV >> 2) + (layer - 1) * HH];
            #pragma unroll
            for (int nt = 0; nt < 16; nt++) {
                float2 b2v = *(float2*)&bv[8 * nt + c2];
                #pragma unroll
                for (int m = 0; m < 2; m++) {
                    acc[m][nt][0] = b2v.x; acc[m][nt][1] = b2v.y;
                    acc[m][nt][2] = b2v.x; acc[m][nt][3] = b2v.y;
                }
            }
        }

        // ---- 2 half-layer stages; double-buffered cp.async pipeline ----
        #pragma unroll
        for (int hf = 0; hf < 2; hf++) {
            if (s + 1 < 6) {
                const char* src = (const char*)g_Wp + (s + 1) * 16384 + tid * 16;
                uint32_t dst = sb + OFF_B + ((s + 1) & 1) * 16384 + tid * 16;
                #pragma unroll
                for (int i = 0; i < 8; i++)
                    CP_ASYNC16(dst + i * 2048, src + i * 2048);
                CP_COMMIT();
                CP_WAIT1();
            } else {
                CP_WAIT0();
            }
            __syncthreads();   // stage s data visible

            const uint32_t baseB = sb + OFF_B + (uint32_t)((s & 1) * 16384)
                                 + (uint32_t)rB * 256;
            #pragma unroll
            for (int ks = 0; ks < 8; ks++) {
                uint32_t ah0[4], ah1[4];
                const uint32_t kA = (uint32_t)(2 * ks) + cselA;
                const uint32_t kB = (uint32_t)(2 * ks) + cselB;
                ldm4(ah0, baseA0 + ((kA ^ parA0) << 4));
                ldm4(ah1, baseA1 + ((kA ^ parA1) << 4));
                #pragma unroll
                for (int q2 = 0; q2 < 2; q2++) {
                    uint32_t bh[2][4];
                    const uint32_t baseBq = baseB + (uint32_t)q2 * 8192;
                    #pragma unroll
                    for (int jj = 0; jj < 2; jj++)
                        ldm4(bh[jj], baseBq + jj * 4096 + ((kB ^ parB) << 4));
                    #pragma unroll
                    for (int tt = 0; tt < 4; tt++) {
                        const int nt = 4 * (2 * hf + q2) + tt;
                        const uint32_t* bH = &bh[tt >> 1][(tt & 1) << 1];
                        mma_f16(acc[0][nt], ah0, bH);
                        mma_f16(acc[1][nt], ah1, bH);
                    }
                }
            }
            s++;
            __syncthreads();   // all warps done with this buffer
        }

        if (layer < 2) {
            // ---- epilogue: gelu -> A plane (fp16, swizzled) ----
            const int r0 = (w << 5) + (l >> 2);
            #pragma unroll
            for (int m = 0; m < 2; m++) {
                const int ra = r0 + 16 * m, rb = ra + 8;
                const uint32_t sa  = (uint32_t)ra * 256 + (uint32_t)((l & 3) << 2);
                const uint32_t sbt = (uint32_t)rb * 256 + (uint32_t)((l & 3) << 2);
                #pragma unroll
                for (int nt = 0; nt < 16; nt++) {
                    uint32_t hA = packh2(gelu_fast(acc[m][nt][0]),
                                         gelu_fast(acc[m][nt][1]));
                    uint32_t hB = packh2(gelu_fast(acc[m][nt][2]),
                                         gelu_fast(acc[m][nt][3]));
                    uint32_t oa = sa  + (uint32_t)((nt ^ (ra & 7)) << 4);
                    uint32_t ob = sbt + (uint32_t)((nt ^ (rb & 7)) << 4);
                    *(uint32_t*)(smem + OFF_A + oa) = hA;
                    *(uint32_t*)(smem + OFF_A + ob) = hB;
                }
            }
            __syncthreads();
        } else {
            // ---- final: gelu*valid, reduce 32 edges -> per-node msum ----
            const int rr = (w << 5) + (l >> 2);
            const float vl0 = smf[(OFF_VLD >> 2) + rr];
            const float vl1 = smf[(OFF_VLD >> 2) + rr + 8];
            const float vl2 = smf[(OFF_VLD >> 2) + rr + 16];
            const float vl3 = smf[(OFF_VLD >> 2) + rr + 24];
            #pragma unroll
            for (int nt = 0; nt < 16; nt++) {
                float s0 = gelu_fast(acc[0][nt][0]) * vl0
                         + gelu_fast(acc[0][nt][2]) * vl1
                         + gelu_fast(acc[1][nt][0]) * vl2
                         + gelu_fast(acc[1][nt][2]) * vl3;
                float s1 = gelu_fast(acc[0][nt][1]) * vl0
                         + gelu_fast(acc[0][nt][3]) * vl1
                         + gelu_fast(acc[1][nt][1]) * vl2
                         + gelu_fast(acc[1][nt][3]) * vl3;
                #pragma unroll
                for (int sh = 4; sh < 32; sh <<= 1) {
                    s0 += __shfl_xor_sync(0xffffffffu, s0, sh);
                    s1 += __shfl_xor_sync(0xffffffffu, s1, sh);
                }
                if (l < 4) {
                    smf[(OFF_MSUM >> 2) + w * HH + 8 * nt + c2]     = s0;
                    smf[(OFF_MSUM >> 2) + w * HH + 8 * nt + c2 + 1] = s1;
                }
            }
            __syncthreads();
            #pragma unroll
            for (int g = 0; g < 4; g++) {
                float ms  = smf[(OFF_MSUM >> 2) + g * HH + tid];
                float upd = smf[(OFF_SELF >> 2) + g * HH + tid]
                          + ms * smf[(OFF_INV >> 2) + g] * smf[(OFF_NM >> 2) + g];
                g_upd[(size_t)(base_node + g) * HH + tid] = upd;
            }
        }
    }
}

// ---------------- graph norm: two-stage coalesced stats ----------------
// stage A: 512 blocks, each sums a contiguous 32-node chunk (coalesced rows)
__global__ __launch_bounds__(256)
void stats_a(const float* __restrict__ atom_mask)
{
    const int blk = blockIdx.x;
    const int b = blk >> 7, chunk = blk & 127;
    const int t = threadIdx.x;
    const int half = t >> 7, col = t & 127;
    const float* base = g_upd + ((size_t)(b * NN) + chunk * 32) * HH;

    // count valid nodes in chunk (warp 0, lanes 0..31)
    float c = (t < 32) ? atom_mask[b * NN + chunk * 32 + t] : 0.0f;
    #pragma unroll
    for (int sh = 16; sh > 0; sh >>= 1)
        c += __shfl_xor_sync(0xffffffffu, c, sh);
    if (t == 0) g_pc[b * 128 + chunk] = c;

    float s = 0.0f, q = 0.0f;
    #pragma unroll
    for (int i = 0; i < 16; i++) {
        float v = base[(2 * i + half) * HH + col];
        s += v; q = fmaf(v, v, q);
    }
    __shared__ float ss[256], sq[256];
    ss[t] = s; sq[t] = q;
    __syncthreads();
    if (t < 128) {
        g_ps[(b * 128 + chunk) * HH + t] = ss[t] + ss[t + 128];
        g_pq[(b * 128 + chunk) * HH + t] = sq[t] + sq[t + 128];
    }
}

// stage B: one block combines 128 partials per (b,h)
__global__ __launch_bounds__(512)
void stats_b()
{
    const int t = threadIdx.x;          // t = b*128 + h
    const int b = t >> 7, h = t & 127;
    float s = 0.0f, q = 0.0f, c = 0.0f;
    #pragma unroll 8
    for (int ch = 0; ch < 128; ch++) {
        s += g_ps[(b * 128 + ch) * HH + h];
        q += g_pq[(b * 128 + ch) * HH + h];
        c += g_pc[b * 128 + ch];
    }
    if (c == 0.0f) c = 1.0f;
    float mean = s / c;
    float var = (q - 2.0f * mean * s + (float)NN * mean * mean) / c;
    g_mean[t] = mean;
    g_rstd[t] = rsqrtf(var + 1e-5f);
}

__global__ __launch_bounds__(256)
void norm_kernel(float* __restrict__ out,
                 const float* __restrict__ atom_mask,
                 const float* __restrict__ scale,
                 const float* __restrict__ shift)
{
    const int i = blockIdx.x * 256 + threadIdx.x;
    if (i >= NODES * HH) return;
    const int h  = i & (HH - 1);
    const int bn = i >> 7;
    const int b  = bn >> 12;
    const float v = g_upd[i];
    out[i] = ((v - g_mean[b * HH + h]) * g_rstd[b * HH + h] * scale[h] + shift[h])
             * atom_mask[bn];
}

__global__ __launch_bounds__(256)
void passthru_kernel(float* __restrict__ out,
                     const float* __restrict__ atom_mask,
                     const float* __restrict__ dist,
                     const int*   __restrict__ edge)
{
    const int M0 = NODES;
    const int M1 = NODES * KK;
    const int total = M0 + 2 * M1;
    const int i = blockIdx.x * 256 + threadIdx.x;
    if (i >= total) return;
    if (i < M0)            out[i] = atom_mask[i];
    else if (i < M0 + M1)  out[i] = dist[i - M0];
    else                   out[i] = (float)edge[i - M0 - M1];
}

extern "C" void kernel_launch(void* const* d_in, const int* in_sizes, int n_in,
                              void* d_out, int out_size)
{
    const float* atom_encode = (const float*)d_in[0];
    const float* atom_mask   = (const float*)d_in[1];
    const float* dist        = (const float*)d_in[2];
    const int*   edge_index  = (const int*)  d_in[3];
    const float* W0 = (const float*)d_in[4];
    const float* b0 = (const float*)d_in[5];
    const float* b1 = (const float*)d_in[7];
    const float* b2 = (const float*)d_in[9];
    const float* scale = (const float*)d_in[10];
    const float* shift = (const float*)d_in[11];
    float* out = (float*)d_out;

    cudaFuncSetAttribute(mpnn_tc, cudaFuncAttributeMaxDynamicSharedMemorySize,
                         SMEM_BYTES);
    cudaFuncSetAttribute(sbias_kernel, cudaFuncAttributeMaxDynamicSharedMemorySize,
                         SB_SMEM);

    prep_weights<<<(4 * HH * HH + 255) / 256, 256>>>(
        (const float*)d_in[4], (const float*)d_in[6], (const float*)d_in[8]);
    sbias_kernel<<<NODES / 128, 128, SB_SMEM>>>(atom_encode, atom_mask, b0);
    mpnn_tc<<<NODES / 4, 128, SMEM_BYTES>>>(atom_encode, atom_mask, dist,
                                            edge_index, W0, b1, b2);
    stats_a<<<BB * 128, 256>>>(atom_mask);
    stats_b<<<1, 512>>>();

    const int OUT0 = NODES * HH;
    norm_kernel<<<(OUT0 + 255) / 256, 256>>>(out, atom_mask, scale, shift);

    const int PT = NODES + 2 * NODES * KK;
    if (out_size >= OUT0 + PT) {
        passthru_kernel<<<(PT + 255) / 256, 256>>>(out + OUT0, atom_mask, dist,
                                                   edge_index);
    }
}

// round 16
// speedup vs baseline: 1.0381x; 1.0381x over previous
#include <cuda_runtime.h>
#include <cuda_fp16.h>
#include <cstdint>
#include <math.h>

#define BB 4
#define NN 4096
#define KK 32
#define HH 128
#define NODES (BB*NN)

// ---------------- scratch (static, no allocation) ----------------
__device__ float g_upd[NODES * HH];          // 8 MB
__device__ float g_sbias[NODES * HH];        // 8 MB: b0 + self@W0_self per node
__device__ float g_mean[BB * HH];
__device__ float g_rstd[BB * HH];
// stats partials: 128 chunks of 32 nodes per batch
__device__ float g_ps[BB * 128 * HH];
__device__ float g_pq[BB * 128 * HH];
__device__ float g_pc[BB * 128];
// prepped fp16 weights:
//   [0, 98304)       : layers 0..2, hi-only, 32 KB each (4 quarters x 8 KB, swizzled)
//   [98304, 163840)  : W0_self hi/lo, 4 quarters x (hi 8 KB | lo 8 KB)
__device__ __align__(16) unsigned char g_Wp[163840];

// ---------------- helpers ----------------
__device__ __forceinline__ uint32_t smem_u32(const void* p) {
    uint32_t a;
    asm("{ .reg .u64 t; cvta.to.shared.u64 t, %1; cvt.u32.u64 %0, t; }"
        : "=r"(a) : "l"(p));
    return a;
}
// fast GELU: tanh form with hardware tanh.approx (sm_75+), ~6 ops.
__device__ __forceinline__ float gelu_fast(float x) {
    float x2 = x * x;
    float y  = x * fmaf(0.03567740814f, x2, 0.7978845608f);
    float t;
    asm("tanh.approx.f32 %0, %1;" : "=f"(t) : "f"(y));
    float h = 0.5f * x;
    return fmaf(h, t, h);
}
__device__ __forceinline__ uint32_t packh2(float x, float y) {
    __half2 h = __floats2half2_rn(x, y);
    return *(uint32_t*)&h;
}
__device__ __forceinline__ void ldm4(uint32_t* r, uint32_t addr) {
    asm volatile("ldmatrix.sync.aligned.m8n8.x4.shared.b16 {%0,%1,%2,%3}, [%4];"
        : "=r"(r[0]), "=r"(r[1]), "=r"(r[2]), "=r"(r[3]) : "r"(addr));
}
__device__ __forceinline__ void mma_f16(float* c, const uint32_t* a, const uint32_t* b) {
    asm volatile(
        "mma.sync.aligned.m16n8k16.row.col.f32.f16.f16.f32 "
        "{%0,%1,%2,%3}, {%4,%5,%6,%7}, {%8,%9}, {%0,%1,%2,%3};"
        : "+f"(c[0]), "+f"(c[1]), "+f"(c[2]), "+f"(c[3])
        : "r"(a[0]), "r"(a[1]), "r"(a[2]), "r"(a[3]), "r"(b[0]), "r"(b[1]));
}
#define CP_ASYNC16(dst, src) \
    asm volatile("cp.async.cg.shared.global [%0], [%1], 16;" \
        :: "r"(dst), "l"(src) : "memory")
#define CP_COMMIT() asm volatile("cp.async.commit_group;" ::: "memory")
#define CP_WAIT1()  asm volatile("cp.async.wait_group 1;" ::: "memory")
#define CP_WAIT0()  asm volatile("cp.async.wait_group 0;" ::: "memory")

// ---------------- prep: W -> fp16, swizzled, quartered ----------------
__global__ void prep_weights(const float* __restrict__ W0,
                             const float* __restrict__ W1,
                             const float* __restrict__ W2)
{
    int i = blockIdx.x * blockDim.x + threadIdx.x;
    if (i >= 4 * HH * HH) return;
    int lyr = i >> 14, r = i & 16383, n = r >> 7, k = r & 127;
    float v;
    if (lyr == 0)      v = W0[k * HH + n];            // src block rows 0..127
    else if (lyr == 1) v = W1[k * HH + n];
    else if (lyr == 2) v = W2[k * HH + n];
    else               v = W0[(HH + k) * HH + n];     // self block rows 128..255
    __half h = __float2half_rn(v);
    int q = n >> 5, nl = n & 31;
    int byte = nl * 256 + (((k >> 3) ^ (nl & 7)) << 4) + ((k & 7) << 1);
    if (lyr < 3) {
        *(__half*)(g_Wp + lyr * 32768 + q * 8192 + byte) = h;
    } else {
        __half lo = __float2half_rn(v - __half2float(h));
        unsigned char* base = g_Wp + 98304 + q * 16384;
        *(__half*)(base + byte)        = h;
        *(__half*)(base + 8192 + byte) = lo;
    }
}

// ---------------- self-bias mini-GEMM: g_sbias = b0 + self@W0_self ----------------
#define SB_SMEM 98304
__global__ __launch_bounds__(128)
void sbias_kernel(const float* __restrict__ enc, const float* __restrict__ mask,
                  const float* __restrict__ b0)
{
    extern __shared__ char smem[];
    uint32_t sb = smem_u32(smem);
    const int tid = threadIdx.x;
    const int w = tid >> 5, l = tid & 31;
    const int base_node = blockIdx.x << 7;

    // gather masked self rows into fp16 A plane
    {
        const int node = base_node + tid;
        const float mm = mask[node];
        const float4* rp = (const float4*)(enc + (size_t)node * HH);
        const int rp7 = tid & 7;
        #pragma unroll
        for (int c = 0; c < 16; c++) {
            float4 v0 = rp[2 * c], v1 = rp[2 * c + 1];
            uint32_t u0 = packh2(v0.x * mm, v0.y * mm);
            uint32_t u1 = packh2(v0.z * mm, v0.w * mm);
            uint32_t u2 = packh2(v1.x * mm, v1.y * mm);
            uint32_t u3 = packh2(v1.z * mm, v1.w * mm);
            uint32_t off = (uint32_t)tid * 256 + (uint32_t)((c ^ rp7) << 4);
            *(uint4*)(smem + off) = make_uint4(u0, u1, u2, u3);
        }
    }
    // stage full W0_self hi/lo: 64 KB at +32768
    {
        const uint4* src = (const uint4*)(g_Wp + 98304);
        uint4* dst = (uint4*)(smem + 32768);
        #pragma unroll
        for (int i = 0; i < 32; i++) dst[tid + 128 * i] = src[tid + 128 * i];
    }
    __syncthreads();

    const int rA0 = (w << 5) + (l & 15), rA1 = rA0 + 16;
    const uint32_t cselA = (uint32_t)(l >> 4);
    const uint32_t baseA0 = sb + (uint32_t)rA0 * 256;
    const uint32_t baseA1 = sb + (uint32_t)rA1 * 256;
    const uint32_t parA0 = (uint32_t)(rA0 & 7), parA1 = (uint32_t)(rA1 & 7);
    const int rB = (l & 7) + ((l >> 4) << 3);
    const uint32_t cselB = (uint32_t)((l >> 3) & 1);
    const uint32_t parB = (uint32_t)(rB & 7);
    const int c2 = (l & 3) << 1;

    float acc[2][16][4];
    #pragma unroll
    for (int nt = 0; nt < 16; nt++) {
        float bx = b0[8 * nt + c2], by = b0[8 * nt + c2 + 1];
        #pragma unroll
        for (int m = 0; m < 2; m++) {
            acc[m][nt][0] = bx; acc[m][nt][1] = by;
            acc[m][nt][2] = bx; acc[m][nt][3] = by;
        }
    }

    #pragma unroll
    for (int ks = 0; ks < 8; ks++) {
        uint32_t ah0[4], ah1[4];
        const uint32_t kA = (uint32_t)(2 * ks) + cselA;
        const uint32_t kB = (uint32_t)(2 * ks) + cselB;
        ldm4(ah0, baseA0 + ((kA ^ parA0) << 4));
        ldm4(ah1, baseA1 + ((kA ^ parA1) << 4));
        #pragma unroll
        for (int q = 0; q < 4; q++) {
            const uint32_t baseBq = sb + 32768 + (uint32_t)q * 16384
                                  + (uint32_t)rB * 256;
            uint32_t bh[2][4], bl[2][4];
            #pragma unroll
            for (int jj = 0; jj < 2; jj++) {
                ldm4(bh[jj], baseBq + jj * 4096 + ((kB ^ parB) << 4));
                ldm4(bl[jj], baseBq + 8192 + jj * 4096 + ((kB ^ parB) << 4));
            }
            #pragma unroll
            for (int tt = 0; tt < 4; tt++) {
                const int nt = 4 * q + tt;
                const uint32_t* bH = &bh[tt >> 1][(tt & 1) << 1];
                const uint32_t* bL = &bl[tt >> 1][(tt & 1) << 1];
                mma_f16(acc[0][nt], ah0, bH);
                mma_f16(acc[1][nt], ah1, bH);
                mma_f16(acc[0][nt], ah0, bL);
                mma_f16(acc[1][nt], ah1, bL);
            }
        }
    }

    #pragma unroll
    for (int m = 0; m < 2; m++) {
        const int row0 = base_node + (w << 5) + (m << 4) + (l >> 2);
        #pragma unroll
        for (int nt = 0; nt < 16; nt++) {
            *(float2*)&g_sbias[(size_t)row0 * HH + 8 * nt + c2] =
                make_float2(acc[m][nt][0], acc[m][nt][1]);
            *(float2*)&g_sbias[(size_t)(row0 + 8) * HH + 8 * nt + c2] =
                make_float2(acc[m][nt][2], acc[m][nt][3]);
        }
    }
}

// ---------------- main fused kernel (R12, byte-identical) ----------------
// smem layout (bytes)
#define OFF_A     0        // 32768 : A fp16 plane, 128 rows x 256B, chunk-swizzled
#define OFF_B     32768    // 65536 : double-buffered full-layer weights (2 x 32 KB)
#define OFF_SELF  98304    // 2048
#define OFF_SBIAS 100352   // 2048
#define OFF_MSUM  102400   // 2048 : [4 warps][128]
#define OFF_W256  104448   // 512
#define OFF_BV    104960   // 1024
#define OFF_DE    105984   // 512
#define OFF_VLD   106496   // 512
#define OFF_INV   107008   // 16
#define OFF_NM    107024   // 16
#define SMEM_BYTES 107040

__global__ __launch_bounds__(128)
void mpnn_tc(const float* __restrict__ enc, const float* __restrict__ mask,
             const float* __restrict__ dist, const int* __restrict__ eidx,
             const float* __restrict__ W0,
             const float* __restrict__ b1, const float* __restrict__ b2)
{
    extern __shared__ char smem[];
    uint32_t sb = smem_u32(smem);
    float* smf = (float*)smem;
    const int tid = threadIdx.x;
    const int w = tid >> 5, l = tid & 31;
    const int base_node = blockIdx.x << 2;
    const int batch = base_node >> 12;

    // prologue: prefetch layer-0 weights (32 KB) immediately
    {
        const char* src = (const char*)g_Wp + tid * 16;
        uint32_t dst = sb + OFF_B + tid * 16;
        #pragma unroll
        for (int i = 0; i < 16; i++)
            CP_ASYNC16(dst + i * 2048, src + i * 2048);
        CP_COMMIT();
    }

    // ---- per-edge metadata (thread = edge row) ----
    const int ei = eidx[base_node * KK + tid];
    const int gsrc = batch * NN + ((ei < 0) ? 0 : ei);
    const float smask = mask[gsrc];
    smf[(OFF_DE  >> 2) + tid] = dist[base_node * KK + tid];
    smf[(OFF_VLD >> 2) + tid] = (ei >= 0) ? 1.0f : 0.0f;
    unsigned cnt = __reduce_add_sync(0xffffffffu, (ei >= 0) ? 1u : 0u);
    if (l == 0) smf[(OFF_INV >> 2) + w] = 1.0f / ((cnt == 0) ? 1.0f : (float)cnt);

    #pragma unroll
    for (int g = 0; g < 4; g++) {
        float mm = mask[base_node + g];
        smf[(OFF_SELF  >> 2) + g * HH + tid] =
            enc[(size_t)(base_node + g) * HH + tid] * mm;
        smf[(OFF_SBIAS >> 2) + g * HH + tid] =
            g_sbias[(size_t)(base_node + g) * HH + tid];
    }
    if (tid < 4) smf[(OFF_NM >> 2) + tid] = mask[base_node + tid];
    smf[(OFF_W256 >> 2) + tid]      = W0[256 * HH + tid];
    smf[(OFF_BV   >> 2) + tid]      = b1[tid];
    smf[(OFF_BV   >> 2) + HH + tid] = b2[tid];

    // ---- gather neighbor features -> A plane (fp16, swizzled) ----
    {
        const float4* rp = (const float4*)(enc + (size_t)gsrc * HH);
        const int rp7 = tid & 7;
        #pragma unroll
        for (int c = 0; c < 16; c++) {
            float4 v0 = rp[2 * c], v1 = rp[2 * c + 1];
            uint32_t u0 = packh2(v0.x * smask, v0.y * smask);
            uint32_t u1 = packh2(v0.z * smask, v0.w * smask);
            uint32_t u2 = packh2(v1.x * smask, v1.y * smask);
            uint32_t u3 = packh2(v1.z * smask, v1.w * smask);
            uint32_t off = (uint32_t)tid * 256 + (uint32_t)((c ^ rp7) << 4);
            *(uint4*)(smem + OFF_A + off) = make_uint4(u0, u1, u2, u3);
        }
    }

    // ---- lane constants for ldmatrix addressing ----
    const int rA0 = (w << 5) + (l & 15), rA1 = rA0 + 16;
    const uint32_t cselA = (uint32_t)(l >> 4);
    const uint32_t baseA0 = sb + OFF_A + (uint32_t)rA0 * 256;
    const uint32_t baseA1 = sb + OFF_A + (uint32_t)rA1 * 256;
    const uint32_t parA0 = (uint32_t)(rA0 & 7), parA1 = (uint32_t)(rA1 & 7);
    const int rB = (l & 7) + ((l >> 4) << 3);
    const uint32_t cselB = (uint32_t)((l >> 3) & 1);
    const uint32_t parB = (uint32_t)(rB & 7);
    const int c2 = (l & 3) << 1;

    float de4[4], vl4[4];
    #pragma unroll
    for (int ri = 0; ri < 4; ri++) {
        int rr = (w << 5) + (l >> 2) + 8 * ri;
        de4[ri] = smf[(OFF_DE  >> 2) + rr];
        vl4[ri] = smf[(OFF_VLD >> 2) + rr];
    }
    __syncthreads();   // A plane + small tables visible

    float acc[2][16][4];

    #pragma unroll 1
    for (int layer = 0; layer < 3; layer++) {
        // ---- init acc with bias ----
        if (layer == 0) {
            #pragma unroll
            for (int nt = 0; nt < 16; nt++) {
                float2 sb2 = *(float2*)&smf[(OFF_SBIAS >> 2) + w * HH + 8 * nt + c2];
                float2 w2  = *(float2*)&smf[(OFF_W256  >> 2) + 8 * nt + c2];
                #pragma unroll
                for (int m = 0; m < 2; m++) {
                    acc[m][nt][0] = fmaf(de4[2 * m],     w2.x, sb2.x);
                    acc[m][nt][1] = fmaf(de4[2 * m],     w2.y, sb2.y);
                    acc[m][nt][2] = fmaf(de4[2 * m + 1], w2.x, sb2.x);
                    acc[m][nt][3] = fmaf(de4[2 * m + 1], w2.y, sb2.y);
                }
            }
        } else {
            const float* bv = &smf[(OFF_BV >> 2) + (layer - 1) * HH];
            #pragma unroll
            for (int nt = 0; nt < 16; nt++) {
                float2 b2v = *(float2*)&bv[8 * nt + c2];
                #pragma unroll
                for (int m = 0; m < 2; m++) {
                    acc[m][nt][0] = b2v.x; acc[m][nt][1] = b2v.y;
                    acc[m][nt][2] = b2v.x; acc[m][nt][3] = b2v.y;
                }
            }
        }

        // ---- prefetch next layer's weights; wait for current ----
        if (layer + 1 < 3) {
            const char* src = (const char*)g_Wp + (layer + 1) * 32768 + tid * 16;
            uint32_t dst = sb + OFF_B + ((layer + 1) & 1) * 32768 + tid * 16;
            #pragma unroll
            for (int i = 0; i < 16; i++)
                CP_ASYNC16(dst + i * 2048, src + i * 2048);
            CP_COMMIT();
            CP_WAIT1();
        } else {
            CP_WAIT0();
        }
        __syncthreads();   // current layer weights visible to all warps

        // ---- full layer: ks-outer (A fragments hoisted), q-inner ----
        const uint32_t baseBL = sb + OFF_B + (uint32_t)((layer & 1) * 32768)
                              + (uint32_t)rB * 256;
        #pragma unroll
        for (int ks = 0; ks < 8; ks++) {
            uint32_t ah0[4], ah1[4];
            const uint32_t kA = (uint32_t)(2 * ks) + cselA;
            const uint32_t kB = (uint32_t)(2 * ks) + cselB;
            ldm4(ah0, baseA0 + ((kA ^ parA0) << 4));
            ldm4(ah1, baseA1 + ((kA ^ parA1) << 4));
            #pragma unroll
            for (int q = 0; q < 4; q++) {
                uint32_t bh[2][4];
                const uint32_t baseBq = baseBL + (uint32_t)q * 8192;
                #pragma unroll
                for (int jj = 0; jj < 2; jj++)
                    ldm4(bh[jj], baseBq + jj * 4096 + ((kB ^ parB) << 4));
                #pragma unroll
                for (int tt = 0; tt < 4; tt++) {
                    const int nt = 4 * q + tt;
                    const uint32_t* bH = &bh[tt >> 1][(tt & 1) << 1];
                    mma_f16(acc[0][nt], ah0, bH);
                    mma_f16(acc[1][nt], ah1, bH);
                }
            }
        }
        __syncthreads();   // all warps done with A + this weight buffer

        if (layer < 2) {
            // ---- epilogue: gelu -> A plane (fp16, swizzled) ----
            const int r0 = (w << 5) + (l >> 2);
            #pragma unroll
            for (int m = 0; m < 2; m++) {
                const int ra = r0 + 16 * m, rb = ra + 8;
                const uint32_t sa  = (uint32_t)ra * 256 + (uint32_t)((l & 3) << 2);
                const uint32_t sbt = (uint32_t)rb * 256 + (uint32_t)((l & 3) << 2);
                #pragma unroll
                for (int nt = 0; nt < 16; nt++) {
                    uint32_t hA = packh2(gelu_fast(acc[m][nt][0]),
                                         gelu_fast(acc[m][nt][1]));
                    uint32_t hB = packh2(gelu_fast(acc[m][nt][2]),
                                         gelu_fast(acc[m][nt][3]));
                    uint32_t oa = sa  + (uint32_t)((nt ^ (ra & 7)) << 4);
                    uint32_t ob = sbt + (uint32_t)((nt ^ (rb & 7)) << 4);
                    *(uint32_t*)(smem + OFF_A + oa) = hA;
                    *(uint32_t*)(smem + OFF_A + ob) = hB;
                }
            }
            __syncthreads();
        } else {
            // ---- final: gelu*valid, reduce 32 edges -> per-node msum ----
            #pragma unroll
            for (int nt = 0; nt < 16; nt++) {
                float s0 = gelu_fast(acc[0][nt][0]) * vl4[0]
                         + gelu_fast(acc[0][nt][2]) * vl4[1]
                         + gelu_fast(acc[1][nt][0]) * vl4[2]
                         + gelu_fast(acc[1][nt][2]) * vl4[3];
                float s1 = gelu_fast(acc[0][nt][1]) * vl4[0]
                         + gelu_fast(acc[0][nt][3]) * vl4[1]
                         + gelu_fast(acc[1][nt][1]) * vl4[2]
                         + gelu_fast(acc[1][nt][3]) * vl4[3];
                #pragma unroll
                for (int sh = 4; sh < 32; sh <<= 1) {
                    s0 += __shfl_xor_sync(0xffffffffu, s0, sh);
                    s1 += __shfl_xor_sync(0xffffffffu, s1, sh);
                }
                if (l < 4) {
                    smf[(OFF_MSUM >> 2) + w * HH + 8 * nt + c2]     = s0;
                    smf[(OFF_MSUM >> 2) + w * HH + 8 * nt + c2 + 1] = s1;
                }
            }
            __syncthreads();
            #pragma unroll
            for (int g = 0; g < 4; g++) {
                float ms  = smf[(OFF_MSUM >> 2) + g * HH + tid];
                float upd = smf[(OFF_SELF >> 2) + g * HH + tid]
                          + ms * smf[(OFF_INV >> 2) + g] * smf[(OFF_NM >> 2) + g];
                g_upd[(size_t)(base_node + g) * HH + tid] = upd;
            }
        }
    }
}

// ---------------- graph norm: two-stage coalesced stats (512-block stage A) ----
__global__ __launch_bounds__(256)
void stats_a(const float* __restrict__ atom_mask)
{
    const int blk = blockIdx.x;
    const int b = blk >> 7, chunk = blk & 127;
    const int t = threadIdx.x;
    const int half = t >> 7, col = t & 127;
    const float* base = g_upd + ((size_t)(b * NN) + chunk * 32) * HH;

    // count valid nodes in chunk (warp 0, lanes 0..31)
    float c = (t < 32) ? atom_mask[b * NN + chunk * 32 + t] : 0.0f;
    #pragma unroll
    for (int sh = 16; sh > 0; sh >>= 1)
        c += __shfl_xor_sync(0xffffffffu, c, sh);
    if (t == 0) g_pc[b * 128 + chunk] = c;

    float s = 0.0f, q = 0.0f;
    #pragma unroll
    for (int i = 0; i < 16; i++) {
        float v = base[(2 * i + half) * HH + col];
        s += v; q = fmaf(v, v, q);
    }
    __shared__ float ss[256], sq[256];
    ss[t] = s; sq[t] = q;
    __syncthreads();
    if (t < 128) {
        g_ps[(b * 128 + chunk) * HH + t] = ss[t] + ss[t + 128];
        g_pq[(b * 128 + chunk) * HH + t] = sq[t] + sq[t + 128];
    }
}

__global__ __launch_bounds__(512)
void stats_b()
{
    const int t = threadIdx.x;          // t = b*128 + h
    const int b = t >> 7, h = t & 127;
    float s = 0.0f, q = 0.0f, c = 0.0f;
    #pragma unroll 8
    for (int ch = 0; ch < 128; ch++) {
        s += g_ps[(b * 128 + ch) * HH + h];
        q += g_pq[(b * 128 + ch) * HH + h];
        c += g_pc[b * 128 + ch];
    }
    if (c == 0.0f) c = 1.0f;
    float mean = s / c;
    float var = (q - 2.0f * mean * s + (float)NN * mean * mean) / c;
    g_mean[t] = mean;
    g_rstd[t] = rsqrtf(var + 1e-5f);
}

// ---------------- norm: float4 vectorized ----------------
__global__ __launch_bounds__(256)
void norm_kernel(float* __restrict__ out,
                 const float* __restrict__ atom_mask,
                 const float* __restrict__ scale,
                 const float* __restrict__ shift)
{
    const int i4 = blockIdx.x * 256 + threadIdx.x;       // float4 index
    if (i4 >= NODES * HH / 4) return;
    const int h4 = (i4 & 31) << 2;                        // h = h4..h4+3
    const int bn = i4 >> 5;
    const int b  = bn >> 12;
    const float mk = atom_mask[bn];
    float4 v  = *(const float4*)&g_upd[(size_t)i4 * 4];
    float4 mn = *(const float4*)&g_mean[b * HH + h4];
    float4 rs = *(const float4*)&g_rstd[b * HH + h4];
    float4 sc = *(const float4*)&scale[h4];
    float4 sh = *(const float4*)&shift[h4];
    float4 o;
    o.x = fmaf((v.x - mn.x) * rs.x, sc.x, sh.x) * mk;
    o.y = fmaf((v.y - mn.y) * rs.y, sc.y, sh.y) * mk;
    o.z = fmaf((v.z - mn.z) * rs.z, sc.z, sh.z) * mk;
    o.w = fmaf((v.w - mn.w) * rs.w, sc.w, sh.w) * mk;
    *(float4*)&out[(size_t)i4 * 4] = o;
}

// ---------------- passthru: float4 vectorized ----------------
__global__ __launch_bounds__(256)
void passthru_kernel(float* __restrict__ out,
                     const float* __restrict__ atom_mask,
                     const float* __restrict__ dist,
                     const int*   __restrict__ edge)
{
    const int Q0 = NODES / 4;            // 4096  mask float4s
    const int Q1 = NODES * KK / 4;       // 131072 dist float4s
    const int total = Q0 + 2 * Q1;
    const int i = blockIdx.x * 256 + threadIdx.x;
    if (i >= total) return;
    if (i < Q0) {
        *(float4*)&out[(size_t)i * 4] = *(const float4*)&atom_mask[(size_t)i * 4];
    } else if (i < Q0 + Q1) {
        const int j = i - Q0;
        *(float4*)&out[(size_t)i * 4] = *(const float4*)&dist[(size_t)j * 4];
    } else {
        const int j = i - Q0 - Q1;
        int4 e = *(const int4*)&edge[(size_t)j * 4];
        float4 o = make_float4((float)e.x, (float)e.y, (float)e.z, (float)e.w);
        *(float4*)&out[(size_t)i * 4] = o;
    }
}

extern "C" void kernel_launch(void* const* d_in, const int* in_sizes, int n_in,
                              void* d_out, int out_size)
{
    const float* atom_encode = (const float*)d_in[0];
    const float* atom_mask   = (const float*)d_in[1];
    const float* dist        = (const float*)d_in[2];
    const int*   edge_index  = (const int*)  d_in[3];
    const float* W0 = (const float*)d_in[4];
    const float* b0 = (const float*)d_in[5];
    const float* b1 = (const float*)d_in[7];
    const float* b2 = (const float*)d_in[9];
    const float* scale = (const float*)d_in[10];
    const float* shift = (const float*)d_in[11];
    float* out = (float*)d_out;

    cudaFuncSetAttribute(mpnn_tc, cudaFuncAttributeMaxDynamicSharedMemorySize,
                         SMEM_BYTES);
    cudaFuncSetAttribute(sbias_kernel, cudaFuncAttributeMaxDynamicSharedMemorySize,
                         SB_SMEM);

    prep_weights<<<(4 * HH * HH + 255) / 256, 256>>>(
        (const float*)d_in[4], (const float*)d_in[6], (const float*)d_in[8]);
    sbias_kernel<<<NODES / 128, 128, SB_SMEM>>>(atom_encode, atom_mask, b0);
    mpnn_tc<<<NODES / 4, 128, SMEM_BYTES>>>(atom_encode, atom_mask, dist,
                                            edge_index, W0, b1, b2);
    stats_a<<<BB * 128, 256>>>(atom_mask);
    stats_b<<<1, 512>>>();

    const int OUT0_Q = NODES * HH / 4;                 // float4 count
    norm_kernel<<<(OUT0_Q + 255) / 256, 256>>>(out, atom_mask, scale, shift);

    const int OUT0 = NODES * HH;
    const int PT = NODES + 2 * NODES * KK;
    if (out_size >= OUT0 + PT) {
        const int PTQ = PT / 4;
        passthru_kernel<<<(PTQ + 255) / 256, 256>>>(out + OUT0, atom_mask, dist,
                                                    edge_index);
    }
}